// round 1
// baseline (speedup 1.0000x reference)
#include <cuda_runtime.h>
#include <cuda_bf16.h>
#include <math.h>

// ---------------------------------------------------------------------------
// HawkBlock: B=4, T=4096, HIDDEN=1024, D_REC=2048, INTER=4096
//   h   = rmsnorm(x, ln1)
//   xin = h @ w_in^T            gate = sigmoid(h @ w_gate^T)
//   a   = sigmoid(a_param + xin @ w_a^T)
//   y   = gate * hawk_scan(xin, a)
//   xr  = x + y @ w_out^T
//   h2  = rmsnorm(xr, ln2)
//   out = xr + (silu(h2@Wg^T) * (h2@Wu^T)) @ Wd^T
// ---------------------------------------------------------------------------

#define NTOK   16384        // B*T
#define HIDDEN 1024
#define DREC   2048
#define INTER  4096
#define TLEN   4096
#define NB     4

// ---- static scratch (no allocations allowed) ----
__device__ float g_h   [(size_t)NTOK * HIDDEN];
__device__ float g_h2  [(size_t)NTOK * HIDDEN];
__device__ float g_xres[(size_t)NTOK * HIDDEN];
__device__ float g_xin [(size_t)NTOK * DREC];
__device__ float g_gate[(size_t)NTOK * DREC];
__device__ float g_a   [(size_t)NTOK * DREC];
__device__ float g_y   [(size_t)NTOK * DREC];
__device__ float g_mg  [(size_t)NTOK * INTER];
__device__ float g_mu  [(size_t)NTOK * INTER];

// ---------------------------------------------------------------------------
// RMSNorm: one block per token, 256 threads, 4 floats (1 float4) per thread.
// ---------------------------------------------------------------------------
__global__ __launch_bounds__(256) void rmsnorm_kernel(
    const float* __restrict__ x, const float* __restrict__ w,
    float* __restrict__ out)
{
    int tkn = blockIdx.x;
    int t = threadIdx.x;
    const float4* xp = reinterpret_cast<const float4*>(x + (size_t)tkn * HIDDEN);
    float4 v = xp[t];
    float s = v.x * v.x + v.y * v.y + v.z * v.z + v.w * v.w;
    #pragma unroll
    for (int o = 16; o > 0; o >>= 1) s += __shfl_xor_sync(0xFFFFFFFFu, s, o);
    __shared__ float ws[8];
    __shared__ float tot_sh;
    if ((t & 31) == 0) ws[t >> 5] = s;
    __syncthreads();
    if (t < 32) {
        float z = (t < 8) ? ws[t] : 0.0f;
        #pragma unroll
        for (int o = 4; o > 0; o >>= 1) z += __shfl_xor_sync(0xFFFFFFFFu, z, o);
        if (t == 0) tot_sh = z;
    }
    __syncthreads();
    float r = rsqrtf(tot_sh * (1.0f / HIDDEN) + 1e-6f);
    float4 wv = reinterpret_cast<const float4*>(w)[t];
    float4 o4;
    o4.x = v.x * r * wv.x; o4.y = v.y * r * wv.y;
    o4.z = v.z * r * wv.z; o4.w = v.w * r * wv.w;
    reinterpret_cast<float4*>(out + (size_t)tkn * HIDDEN)[t] = o4;
}

// ---------------------------------------------------------------------------
// SGEMM: C[N,M] = A[N,K] @ W[M,K]^T  with fused epilogue.
// BM=BN=128, BK=16, 256 threads, 8x8 microtile via float4 smem reads.
// All dims divisible by tile sizes (no bounds checks).
// ---------------------------------------------------------------------------
#define BM 128
#define BN 128
#define BK 16

#define EPI_NONE          0
#define EPI_SIGMOID       1
#define EPI_BIAS_SIGMOID  2   // aux = bias[col]
#define EPI_RESADD        3   // aux = residual[idx]
#define EPI_SILU_AUX_MUL  4   // aux = g[idx];  out = silu(g) * acc

template<int EPI>
__device__ __forceinline__ float epi_apply(float v, const float* __restrict__ aux,
                                           size_t idx, int col)
{
    if (EPI == EPI_SIGMOID)      return 1.0f / (1.0f + expf(-v));
    if (EPI == EPI_BIAS_SIGMOID) { float z = v + __ldg(&aux[col]);
                                   return 1.0f / (1.0f + expf(-z)); }
    if (EPI == EPI_RESADD)       return v + __ldg(&aux[idx]);
    if (EPI == EPI_SILU_AUX_MUL) { float g = __ldg(&aux[idx]);
                                   return v * (g / (1.0f + expf(-g))); }
    return v;
}

template<int EPI>
__global__ __launch_bounds__(256) void sgemm_kernel(
    const float* __restrict__ A,   // [N,K] row-major
    const float* __restrict__ W,   // [M,K] row-major
    float* __restrict__ C,         // [N,M] row-major
    const float* __restrict__ aux,
    int N, int M, int K)
{
    __shared__ float As[BK][BM];
    __shared__ float Bs[BK][BN];

    const int tid = threadIdx.x;
    const int tx = tid & 15;   // 0..15  -> output cols
    const int ty = tid >> 4;   // 0..15  -> output rows

    const int rowBlock = blockIdx.y * BM;   // token dim
    const int colBlock = blockIdx.x * BN;   // feature dim

    const float* Aptr = A + (size_t)rowBlock * K;
    const float* Wptr = W + (size_t)colBlock * K;

    float acc[8][8];
    #pragma unroll
    for (int i = 0; i < 8; i++)
        #pragma unroll
        for (int j = 0; j < 8; j++) acc[i][j] = 0.0f;

    for (int kt = 0; kt < K; kt += BK) {
        // load 128x16 tiles of A and W, transposed into smem (As[k][row])
        #pragma unroll
        for (int i = 0; i < 2; i++) {
            int f  = tid + i * 256;       // float4 id, 0..511
            int r  = f >> 2;              // row within tile
            int k4 = (f & 3) * 4;         // k offset of this float4
            float4 va = *reinterpret_cast<const float4*>(Aptr + (size_t)r * K + kt + k4);
            As[k4 + 0][r] = va.x; As[k4 + 1][r] = va.y;
            As[k4 + 2][r] = va.z; As[k4 + 3][r] = va.w;
            float4 vw = *reinterpret_cast<const float4*>(Wptr + (size_t)r * K + kt + k4);
            Bs[k4 + 0][r] = vw.x; Bs[k4 + 1][r] = vw.y;
            Bs[k4 + 2][r] = vw.z; Bs[k4 + 3][r] = vw.w;
        }
        __syncthreads();

        #pragma unroll
        for (int k = 0; k < BK; k++) {
            float4 a0 = *reinterpret_cast<const float4*>(&As[k][ty * 4]);
            float4 a1 = *reinterpret_cast<const float4*>(&As[k][64 + ty * 4]);
            float4 b0 = *reinterpret_cast<const float4*>(&Bs[k][tx * 4]);
            float4 b1 = *reinterpret_cast<const float4*>(&Bs[k][64 + tx * 4]);
            float am[8] = {a0.x, a0.y, a0.z, a0.w, a1.x, a1.y, a1.z, a1.w};
            float bn[8] = {b0.x, b0.y, b0.z, b0.w, b1.x, b1.y, b1.z, b1.w};
            #pragma unroll
            for (int i = 0; i < 8; i++)
                #pragma unroll
                for (int j = 0; j < 8; j++)
                    acc[i][j] = fmaf(am[i], bn[j], acc[i][j]);
        }
        __syncthreads();
    }

    // epilogue + store (float4 per 4 consecutive cols)
    #pragma unroll
    for (int i = 0; i < 8; i++) {
        int r = rowBlock + ((i < 4) ? (ty * 4 + i) : (64 + ty * 4 + i - 4));
        #pragma unroll
        for (int jj = 0; jj < 2; jj++) {
            int c = colBlock + ((jj == 0) ? (tx * 4) : (64 + tx * 4));
            size_t idx = (size_t)r * M + c;
            float4 o;
            o.x = epi_apply<EPI>(acc[i][jj * 4 + 0], aux, idx + 0, c + 0);
            o.y = epi_apply<EPI>(acc[i][jj * 4 + 1], aux, idx + 1, c + 1);
            o.z = epi_apply<EPI>(acc[i][jj * 4 + 2], aux, idx + 2, c + 2);
            o.w = epi_apply<EPI>(acc[i][jj * 4 + 3], aux, idx + 3, c + 3);
            *reinterpret_cast<float4*>(C + idx) = o;
        }
    }
}

// ---------------------------------------------------------------------------
// Hawk scan: h_t = a_t*h_{t-1} + sqrt(1 - a_t^2 + 1e-8)*x_t ; y_t = gate_t*h_t
// One thread per (b, d) channel; coalesced across d (stride-DREC over t).
// ---------------------------------------------------------------------------
__global__ __launch_bounds__(256) void hawk_scan_kernel(
    const float* __restrict__ xin, const float* __restrict__ a,
    const float* __restrict__ gate, float* __restrict__ y)
{
    int ch = blockIdx.x * blockDim.x + threadIdx.x;
    if (ch >= NB * DREC) return;
    int b = ch >> 11;            // /2048
    int d = ch & (DREC - 1);
    size_t base = (size_t)b * TLEN * DREC + d;

    float h = 0.0f;
    #pragma unroll 4
    for (int t = 0; t < TLEN; t++) {
        size_t idx = base + (size_t)t * DREC;
        float at = __ldg(&a[idx]);
        float xt = __ldg(&xin[idx]);
        float gt = __ldg(&gate[idx]);
        float s  = sqrtf(fmaf(-at, at, 1.0f) + 1e-8f);
        h = fmaf(at, h, s * xt);
        y[idx] = gt * h;
    }
}

// ---------------------------------------------------------------------------
// Launch
// ---------------------------------------------------------------------------
extern "C" void kernel_launch(void* const* d_in, const int* in_sizes, int n_in,
                              void* d_out, int out_size)
{
    const float* x       = (const float*)d_in[0];
    const float* ln1_w   = (const float*)d_in[1];
    const float* ln2_w   = (const float*)d_in[2];
    const float* w_in    = (const float*)d_in[3];
    const float* w_gate  = (const float*)d_in[4];
    const float* a_param = (const float*)d_in[5];
    const float* w_a     = (const float*)d_in[6];
    const float* w_out   = (const float*)d_in[7];
    const float* w_mg    = (const float*)d_in[8];
    const float* w_mu    = (const float*)d_in[9];
    const float* w_md    = (const float*)d_in[10];
    float* out = (float*)d_out;

    float *p_h, *p_h2, *p_xres, *p_xin, *p_gate, *p_a, *p_y, *p_mg, *p_mu;
    cudaGetSymbolAddress((void**)&p_h,    g_h);
    cudaGetSymbolAddress((void**)&p_h2,   g_h2);
    cudaGetSymbolAddress((void**)&p_xres, g_xres);
    cudaGetSymbolAddress((void**)&p_xin,  g_xin);
    cudaGetSymbolAddress((void**)&p_gate, g_gate);
    cudaGetSymbolAddress((void**)&p_a,    g_a);
    cudaGetSymbolAddress((void**)&p_y,    g_y);
    cudaGetSymbolAddress((void**)&p_mg,   g_mg);
    cudaGetSymbolAddress((void**)&p_mu,   g_mu);

    dim3 blk(256);

    // 1) h = rmsnorm(x, ln1)
    rmsnorm_kernel<<<NTOK, blk>>>(x, ln1_w, p_h);

    // 2) xin = h @ w_in^T
    sgemm_kernel<EPI_NONE><<<dim3(DREC / BN, NTOK / BM), blk>>>(
        p_h, w_in, p_xin, nullptr, NTOK, DREC, HIDDEN);

    // 3) gate = sigmoid(h @ w_gate^T)
    sgemm_kernel<EPI_SIGMOID><<<dim3(DREC / BN, NTOK / BM), blk>>>(
        p_h, w_gate, p_gate, nullptr, NTOK, DREC, HIDDEN);

    // 4) a = sigmoid(a_param + xin @ w_a^T)
    sgemm_kernel<EPI_BIAS_SIGMOID><<<dim3(DREC / BN, NTOK / BM), blk>>>(
        p_xin, w_a, p_a, a_param, NTOK, DREC, DREC);

    // 5) y = gate * scan(xin, a)
    hawk_scan_kernel<<<(NB * DREC + 255) / 256, blk>>>(p_xin, p_a, p_gate, p_y);

    // 6) xres = x + y @ w_out^T
    sgemm_kernel<EPI_RESADD><<<dim3(HIDDEN / BN, NTOK / BM), blk>>>(
        p_y, w_out, p_xres, x, NTOK, HIDDEN, DREC);

    // 7) h2 = rmsnorm(xres, ln2)
    rmsnorm_kernel<<<NTOK, blk>>>(p_xres, ln2_w, p_h2);

    // 8) mg = h2 @ w_mlp_gate^T
    sgemm_kernel<EPI_NONE><<<dim3(INTER / BN, NTOK / BM), blk>>>(
        p_h2, w_mg, p_mg, nullptr, NTOK, INTER, HIDDEN);

    // 9) mu = silu(mg) * (h2 @ w_mlp_up^T)
    sgemm_kernel<EPI_SILU_AUX_MUL><<<dim3(INTER / BN, NTOK / BM), blk>>>(
        p_h2, w_mu, p_mu, p_mg, NTOK, INTER, HIDDEN);

    // 10) out = xres + mu @ w_mlp_down^T
    sgemm_kernel<EPI_RESADD><<<dim3(HIDDEN / BN, NTOK / BM), blk>>>(
        p_mu, w_md, out, p_xres, NTOK, HIDDEN, INTER);
}

// round 3
// speedup vs baseline: 3.1540x; 3.1540x over previous
#include <cuda_runtime.h>
#include <cuda_bf16.h>
#include <math.h>
#include <stdint.h>

// ---------------------------------------------------------------------------
// HawkBlock: mma.sync bf16 split-3 GEMMs (compute_103-safe) + parallel scan.
// ---------------------------------------------------------------------------

#define NTOK   16384
#define HIDDEN 1024
#define DREC   2048
#define INTER  4096
#define TLEN   4096
#define NB     4

#define SCHUNK   64
#define NCHUNKS  (TLEN / SCHUNK)   // 64
#define NCHAN    (NB * DREC)       // 8192

typedef __nv_bfloat16  bf16;
typedef __nv_bfloat162 bf162;

// ---- static scratch: activations ----
__device__ bf16  g_h_hi  [(size_t)NTOK * HIDDEN];
__device__ bf16  g_h_lo  [(size_t)NTOK * HIDDEN];
__device__ bf16  g_h2_hi [(size_t)NTOK * HIDDEN];
__device__ bf16  g_h2_lo [(size_t)NTOK * HIDDEN];
__device__ float g_xres  [(size_t)NTOK * HIDDEN];
__device__ bf16  g_xin_hi[(size_t)NTOK * DREC];
__device__ bf16  g_xin_lo[(size_t)NTOK * DREC];
__device__ float g_gate  [(size_t)NTOK * DREC];
__device__ float g_a     [(size_t)NTOK * DREC];
__device__ float g_hp    [(size_t)NTOK * DREC];
__device__ float g_P     [(size_t)NTOK * DREC];
__device__ bf16  g_y_hi  [(size_t)NTOK * DREC];
__device__ bf16  g_y_lo  [(size_t)NTOK * DREC];
__device__ float g_mg    [(size_t)NTOK * INTER];
__device__ bf16  g_mu_hi [(size_t)NTOK * INTER];
__device__ bf16  g_mu_lo [(size_t)NTOK * INTER];
__device__ float g_csum  [2 * NCHUNKS * NCHAN];
__device__ float g_carry [NCHUNKS * NCHAN];

// ---- static scratch: split weights (hi/lo bf16) ----
__device__ bf16 g_wi_hi [(size_t)DREC * HIDDEN],  g_wi_lo [(size_t)DREC * HIDDEN];
__device__ bf16 g_wg_hi [(size_t)DREC * HIDDEN],  g_wg_lo [(size_t)DREC * HIDDEN];
__device__ bf16 g_wa_hi [(size_t)DREC * DREC],    g_wa_lo [(size_t)DREC * DREC];
__device__ bf16 g_wo_hi [(size_t)HIDDEN * DREC],  g_wo_lo [(size_t)HIDDEN * DREC];
__device__ bf16 g_wmg_hi[(size_t)INTER * HIDDEN], g_wmg_lo[(size_t)INTER * HIDDEN];
__device__ bf16 g_wmu_hi[(size_t)INTER * HIDDEN], g_wmu_lo[(size_t)INTER * HIDDEN];
__device__ bf16 g_wmd_hi[(size_t)HIDDEN * INTER], g_wmd_lo[(size_t)HIDDEN * INTER];

// ---------------------------------------------------------------------------
// helpers
// ---------------------------------------------------------------------------
__device__ __forceinline__ uint32_t smem_u32(const void* p) {
    uint32_t a;
    asm("{ .reg .u64 t; cvta.to.shared.u64 t, %1; cvt.u32.u64 %0, t; }"
        : "=r"(a) : "l"(p));
    return a;
}
__device__ __forceinline__ void cp16(uint32_t dst, const void* src) {
    asm volatile("cp.async.cg.shared.global [%0], [%1], 16;"
                 :: "r"(dst), "l"(src));
}
__device__ __forceinline__ void cp_commit() {
    asm volatile("cp.async.commit_group;" ::: "memory");
}
template<int N>
__device__ __forceinline__ void cp_wait() {
    asm volatile("cp.async.wait_group %0;" :: "n"(N) : "memory");
}
__device__ __forceinline__ void ldsm4(uint32_t (&r)[4], uint32_t addr) {
    asm volatile("ldmatrix.sync.aligned.m8n8.x4.shared.b16 {%0,%1,%2,%3}, [%4];"
                 : "=r"(r[0]), "=r"(r[1]), "=r"(r[2]), "=r"(r[3]) : "r"(addr));
}
__device__ __forceinline__ void mma_bf16(float (&d)[4], const uint32_t (&a)[4],
                                         uint32_t b0, uint32_t b1) {
    asm volatile("mma.sync.aligned.m16n8k16.row.col.f32.bf16.bf16.f32 "
                 "{%0,%1,%2,%3}, {%4,%5,%6,%7}, {%8,%9}, {%0,%1,%2,%3};"
                 : "+f"(d[0]), "+f"(d[1]), "+f"(d[2]), "+f"(d[3])
                 : "r"(a[0]), "r"(a[1]), "r"(a[2]), "r"(a[3]), "r"(b0), "r"(b1));
}
__device__ __forceinline__ uint32_t pack_bf2(bf16 a, bf16 b) {
    bf162 t = __halves2bfloat162(a, b);
    return *reinterpret_cast<uint32_t*>(&t);
}
__device__ __forceinline__ void split1(float v, bf16& h, bf16& l) {
    h = __float2bfloat16(v);
    l = __float2bfloat16(v - __bfloat162float(h));
}

// ---------------------------------------------------------------------------
// weight split: fp32 -> hi/lo bf16 planes
// ---------------------------------------------------------------------------
__global__ __launch_bounds__(256) void split_w(
    const float* __restrict__ in, bf16* __restrict__ hi, bf16* __restrict__ lo,
    int n4)
{
    int i = blockIdx.x * 256 + threadIdx.x;
    if (i >= n4) return;
    float4 v = reinterpret_cast<const float4*>(in)[i];
    bf16 h0, h1, h2, h3, l0, l1, l2, l3;
    split1(v.x, h0, l0); split1(v.y, h1, l1);
    split1(v.z, h2, l2); split1(v.w, h3, l3);
    reinterpret_cast<uint2*>(hi)[i] = make_uint2(pack_bf2(h0, h1), pack_bf2(h2, h3));
    reinterpret_cast<uint2*>(lo)[i] = make_uint2(pack_bf2(l0, l1), pack_bf2(l2, l3));
}

// ---------------------------------------------------------------------------
// RMSNorm -> hi/lo bf16 planes
// ---------------------------------------------------------------------------
__global__ __launch_bounds__(256) void rmsnorm_split(
    const float* __restrict__ x, const float* __restrict__ w,
    bf16* __restrict__ oh, bf16* __restrict__ ol)
{
    int tkn = blockIdx.x;
    int t = threadIdx.x;
    float4 v = reinterpret_cast<const float4*>(x + (size_t)tkn * HIDDEN)[t];
    float s = v.x * v.x + v.y * v.y + v.z * v.z + v.w * v.w;
    #pragma unroll
    for (int o = 16; o > 0; o >>= 1) s += __shfl_xor_sync(0xFFFFFFFFu, s, o);
    __shared__ float ws[8];
    __shared__ float tot_sh;
    if ((t & 31) == 0) ws[t >> 5] = s;
    __syncthreads();
    if (t < 32) {
        float z = (t < 8) ? ws[t] : 0.0f;
        #pragma unroll
        for (int o = 4; o > 0; o >>= 1) z += __shfl_xor_sync(0xFFFFFFFFu, z, o);
        if (t == 0) tot_sh = z;
    }
    __syncthreads();
    float r = rsqrtf(tot_sh * (1.0f / HIDDEN) + 1e-6f);
    float4 wv = reinterpret_cast<const float4*>(w)[t];
    float f0 = v.x * r * wv.x, f1 = v.y * r * wv.y;
    float f2 = v.z * r * wv.z, f3 = v.w * r * wv.w;
    bf16 h0, h1, h2, h3, l0, l1, l2, l3;
    split1(f0, h0, l0); split1(f1, h1, l1);
    split1(f2, h2, l2); split1(f3, h3, l3);
    size_t q = (size_t)tkn * (HIDDEN / 4) + t;
    reinterpret_cast<uint2*>(oh)[q] = make_uint2(pack_bf2(h0, h1), pack_bf2(h2, h3));
    reinterpret_cast<uint2*>(ol)[q] = make_uint2(pack_bf2(l0, l1), pack_bf2(l2, l3));
}

// ---------------------------------------------------------------------------
// GEMM: C[N=16384, M] = A[N,K] @ W[M,K]^T, bf16 split-3, fp32 accum.
// CTA tile 128x128, BK=64, 8 warps (warp tile 64x32), 2-stage cp.async.
// Smem per stage: Ah,Al,Bh,Bl each 128 rows x 128B (swizzled) = 64KB.
// ---------------------------------------------------------------------------
#define EPI_NONE          0
#define EPI_SIGMOID       1
#define EPI_BIAS_SIGMOID  2
#define EPI_RESADD        3
#define EPI_SILU_AUX_MUL  4

template<int EPI>
__device__ __forceinline__ float epi_apply(float v, const float* __restrict__ aux,
                                           size_t idx, int col)
{
    if (EPI == EPI_SIGMOID)      return 1.0f / (1.0f + expf(-v));
    if (EPI == EPI_BIAS_SIGMOID) { float z = v + __ldg(&aux[col]);
                                   return 1.0f / (1.0f + expf(-z)); }
    if (EPI == EPI_RESADD)       return v + __ldg(&aux[idx]);
    if (EPI == EPI_SILU_AUX_MUL) { float g = __ldg(&aux[idx]);
                                   return v * (g / (1.0f + expf(-g))); }
    return v;
}

#define GEMM_SMEM (2 * 65536)

template<int EPI, bool SPLIT>
__global__ __launch_bounds__(256, 1) void mma_gemm(
    const bf16* __restrict__ Ah, const bf16* __restrict__ Al,
    const bf16* __restrict__ Bh, const bf16* __restrict__ Bl,
    float* __restrict__ Cf, bf16* __restrict__ Ch, bf16* __restrict__ Cl,
    const float* __restrict__ aux, int M, int K)
{
    extern __shared__ char smem[];
    const uint32_t sb = smem_u32(smem);
    const int tid = threadIdx.x;
    const int lane = tid & 31;
    const int wid = tid >> 5;
    const int warp_m = wid >> 2;    // 0..1
    const int warp_n = wid & 3;     // 0..3
    const int rowBlock = blockIdx.y * 128;
    const int colBlock = blockIdx.x * 128;
    const int nch = K >> 6;

    const bf16* gp0 = Ah + (size_t)rowBlock * K;
    const bf16* gp1 = Al + (size_t)rowBlock * K;
    const bf16* gp2 = Bh + (size_t)colBlock * K;
    const bf16* gp3 = Bl + (size_t)colBlock * K;

    auto issue = [&](int s, int c) {
        const int kb = c * 64;
        uint32_t st = sb + (uint32_t)s * 65536u;
        #pragma unroll
        for (int arr = 0; arr < 4; arr++) {
            const bf16* g = (arr == 0) ? gp0 : (arr == 1) ? gp1 : (arr == 2) ? gp2 : gp3;
            uint32_t db = st + arr * 16384u;
            #pragma unroll
            for (int i = 0; i < 4; i++) {
                int u = tid + i * 256;
                int r = u >> 3, cc = u & 7;
                cp16(db + r * 128 + ((cc ^ (r & 7)) << 4),
                     g + (size_t)r * K + kb + cc * 8);
            }
        }
        cp_commit();
    };

    float acc[4][4][4];
    #pragma unroll
    for (int i = 0; i < 4; i++)
        #pragma unroll
        for (int j = 0; j < 4; j++)
            #pragma unroll
            for (int k = 0; k < 4; k++) acc[i][j][k] = 0.0f;

    issue(0, 0);
    issue(1, 1);

    // lane-level ldmatrix addressing
    const int aRow0 = warp_m * 64 + (lane & 7) + ((lane >> 3) & 1) * 8;
    const int aKh   = (lane >> 4) & 1;
    const int bRow0 = warp_n * 32 + ((lane >> 4) & 1) * 8 + (lane & 7);
    const int bKh   = (lane >> 3) & 1;
    const int aSwz  = lane & 7;   // (aRow0 & 7)
    const int bSwz  = lane & 7;   // (bRow0 & 7)

    for (int c = 0; c < nch; c++) {
        int s = c & 1;
        if (c + 1 < nch) cp_wait<1>(); else cp_wait<0>();
        __syncthreads();
        uint32_t st = sb + (uint32_t)s * 65536u;
        #pragma unroll
        for (int pass = 0; pass < 3; pass++) {
            uint32_t aB = st + ((pass == 2) ? 16384u : 0u);
            uint32_t bB = st + ((pass == 1) ? 49152u : 32768u);
            #pragma unroll
            for (int ks = 0; ks < 4; ks++) {
                uint32_t afr[4][4];
                #pragma unroll
                for (int mt = 0; mt < 4; mt++) {
                    uint32_t ad = aB + (uint32_t)(aRow0 + mt * 16) * 128
                                + (uint32_t)(((ks * 2 + aKh) ^ aSwz) << 4);
                    ldsm4(afr[mt], ad);
                }
                uint32_t bfr[4][2];
                #pragma unroll
                for (int p = 0; p < 2; p++) {
                    uint32_t bd = bB + (uint32_t)(bRow0 + p * 16) * 128
                                + (uint32_t)(((ks * 2 + bKh) ^ bSwz) << 4);
                    uint32_t t4[4];
                    ldsm4(t4, bd);
                    bfr[2 * p][0] = t4[0]; bfr[2 * p][1] = t4[1];
                    bfr[2 * p + 1][0] = t4[2]; bfr[2 * p + 1][1] = t4[3];
                }
                #pragma unroll
                for (int mt = 0; mt < 4; mt++)
                    #pragma unroll
                    for (int nt = 0; nt < 4; nt++)
                        mma_bf16(acc[mt][nt], afr[mt], bfr[nt][0], bfr[nt][1]);
            }
        }
        __syncthreads();
        if (c + 2 < nch) issue(s, c + 2);
    }

    // epilogue
    #pragma unroll
    for (int mt = 0; mt < 4; mt++) {
        #pragma unroll
        for (int nt = 0; nt < 4; nt++) {
            int col = colBlock + warp_n * 32 + nt * 8 + (lane & 3) * 2;
            #pragma unroll
            for (int half = 0; half < 2; half++) {
                int row = rowBlock + warp_m * 64 + mt * 16 + (lane >> 2) + half * 8;
                size_t idx = (size_t)row * M + col;
                float f0 = epi_apply<EPI>(acc[mt][nt][half * 2 + 0], aux, idx, col);
                float f1 = epi_apply<EPI>(acc[mt][nt][half * 2 + 1], aux, idx + 1, col + 1);
                if (SPLIT) {
                    bf16 h0, h1, l0, l1;
                    split1(f0, h0, l0); split1(f1, h1, l1);
                    *reinterpret_cast<uint32_t*>(Ch + idx) = pack_bf2(h0, h1);
                    *reinterpret_cast<uint32_t*>(Cl + idx) = pack_bf2(l0, l1);
                } else {
                    *reinterpret_cast<float2*>(Cf + idx) = make_float2(f0, f1);
                }
            }
        }
    }
}

// ---------------------------------------------------------------------------
// Parallel Hawk scan (3 passes)
// ---------------------------------------------------------------------------
__global__ __launch_bounds__(256) void scan_part1(
    const bf16* __restrict__ xh, const bf16* __restrict__ xl,
    const float* __restrict__ a,
    float* __restrict__ hp, float* __restrict__ P, float* __restrict__ csum)
{
    int id = blockIdx.x * 256 + threadIdx.x;
    int chunk = id >> 13;
    int chp = id & (NCHAN - 1);
    int b = chp >> 11;
    int d = chp & (DREC - 1);
    size_t base = ((size_t)b * TLEN + (size_t)chunk * SCHUNK) * DREC + d;

    float h = 0.0f, Aacc = 1.0f;
    #pragma unroll 4
    for (int t = 0; t < SCHUNK; t++) {
        size_t idx = base + (size_t)t * DREC;
        float at = __ldg(&a[idx]);
        float xt = __bfloat162float(__ldg(&xh[idx])) + __bfloat162float(__ldg(&xl[idx]));
        float s = sqrtf(fmaf(-at, at, 1.0f) + 1e-8f);
        h = fmaf(at, h, s * xt);
        Aacc *= at;
        hp[idx] = h;
        P[idx] = Aacc;
    }
    csum[(size_t)chunk * NCHAN + chp] = Aacc;
    csum[(size_t)NCHUNKS * NCHAN + (size_t)chunk * NCHAN + chp] = h;
}

__global__ __launch_bounds__(256) void scan_part2(
    const float* __restrict__ csum, float* __restrict__ carry)
{
    int chp = blockIdx.x * 256 + threadIdx.x;
    float h = 0.0f;
    #pragma unroll 8
    for (int c = 0; c < NCHUNKS; c++) {
        carry[(size_t)c * NCHAN + chp] = h;
        float Ac = csum[(size_t)c * NCHAN + chp];
        float hc = csum[(size_t)NCHUNKS * NCHAN + (size_t)c * NCHAN + chp];
        h = fmaf(Ac, h, hc);
    }
}

__global__ __launch_bounds__(256) void scan_part3(
    const float* __restrict__ hp, const float* __restrict__ P,
    const float* __restrict__ gate, const float* __restrict__ carry,
    bf16* __restrict__ yh, bf16* __restrict__ yl)
{
    size_t q = (size_t)blockIdx.x * 256 + threadIdx.x;  // float4 index
    size_t i = q * 4;
    size_t n = i >> 11;
    int d = (int)(i & (DREC - 1));
    int b = (int)(n >> 12);
    int t = (int)(n & (TLEN - 1));
    int c = t >> 6;

    float4 h4 = reinterpret_cast<const float4*>(hp)[q];
    float4 p4 = reinterpret_cast<const float4*>(P)[q];
    float4 g4 = reinterpret_cast<const float4*>(gate)[q];
    float4 cv = *reinterpret_cast<const float4*>(carry + (size_t)c * NCHAN + b * DREC + d);
    float o0 = g4.x * fmaf(p4.x, cv.x, h4.x);
    float o1 = g4.y * fmaf(p4.y, cv.y, h4.y);
    float o2 = g4.z * fmaf(p4.z, cv.z, h4.z);
    float o3 = g4.w * fmaf(p4.w, cv.w, h4.w);
    bf16 h0, h1, h2, h3, l0, l1, l2, l3;
    split1(o0, h0, l0); split1(o1, h1, l1);
    split1(o2, h2, l2); split1(o3, h3, l3);
    reinterpret_cast<uint2*>(yh)[q] = make_uint2(pack_bf2(h0, h1), pack_bf2(h2, h3));
    reinterpret_cast<uint2*>(yl)[q] = make_uint2(pack_bf2(l0, l1), pack_bf2(l2, l3));
}

// ---------------------------------------------------------------------------
// Launch
// ---------------------------------------------------------------------------
#define SYM(p, s) cudaGetSymbolAddress((void**)&p, s)

extern "C" void kernel_launch(void* const* d_in, const int* in_sizes, int n_in,
                              void* d_out, int out_size)
{
    const float* x       = (const float*)d_in[0];
    const float* ln1_w   = (const float*)d_in[1];
    const float* ln2_w   = (const float*)d_in[2];
    const float* w_in    = (const float*)d_in[3];
    const float* w_gate  = (const float*)d_in[4];
    const float* a_param = (const float*)d_in[5];
    const float* w_a     = (const float*)d_in[6];
    const float* w_out   = (const float*)d_in[7];
    const float* w_mg    = (const float*)d_in[8];
    const float* w_mu    = (const float*)d_in[9];
    const float* w_md    = (const float*)d_in[10];
    float* out = (float*)d_out;

    bf16 *hh, *hl, *h2h, *h2l, *xinh, *xinl, *yh, *yl, *muh, *mul;
    float *xres, *gate, *aa, *hp, *P, *mg, *csum, *carry;
    bf16 *wih, *wil, *wgh, *wgl, *wah, *wal, *woh, *wol;
    bf16 *wmgh, *wmgl, *wmuh, *wmul, *wmdh, *wmdl;

    SYM(hh, g_h_hi);   SYM(hl, g_h_lo);
    SYM(h2h, g_h2_hi); SYM(h2l, g_h2_lo);
    SYM(xinh, g_xin_hi); SYM(xinl, g_xin_lo);
    SYM(yh, g_y_hi);   SYM(yl, g_y_lo);
    SYM(muh, g_mu_hi); SYM(mul, g_mu_lo);
    SYM(xres, g_xres); SYM(gate, g_gate); SYM(aa, g_a);
    SYM(hp, g_hp);     SYM(P, g_P);       SYM(mg, g_mg);
    SYM(csum, g_csum); SYM(carry, g_carry);
    SYM(wih, g_wi_hi);  SYM(wil, g_wi_lo);
    SYM(wgh, g_wg_hi);  SYM(wgl, g_wg_lo);
    SYM(wah, g_wa_hi);  SYM(wal, g_wa_lo);
    SYM(woh, g_wo_hi);  SYM(wol, g_wo_lo);
    SYM(wmgh, g_wmg_hi); SYM(wmgl, g_wmg_lo);
    SYM(wmuh, g_wmu_hi); SYM(wmul, g_wmu_lo);
    SYM(wmdh, g_wmd_hi); SYM(wmdl, g_wmd_lo);

    cudaFuncSetAttribute(mma_gemm<EPI_NONE, true>,          cudaFuncAttributeMaxDynamicSharedMemorySize, GEMM_SMEM);
    cudaFuncSetAttribute(mma_gemm<EPI_NONE, false>,         cudaFuncAttributeMaxDynamicSharedMemorySize, GEMM_SMEM);
    cudaFuncSetAttribute(mma_gemm<EPI_SIGMOID, false>,      cudaFuncAttributeMaxDynamicSharedMemorySize, GEMM_SMEM);
    cudaFuncSetAttribute(mma_gemm<EPI_BIAS_SIGMOID, false>, cudaFuncAttributeMaxDynamicSharedMemorySize, GEMM_SMEM);
    cudaFuncSetAttribute(mma_gemm<EPI_RESADD, false>,       cudaFuncAttributeMaxDynamicSharedMemorySize, GEMM_SMEM);
    cudaFuncSetAttribute(mma_gemm<EPI_SILU_AUX_MUL, true>,  cudaFuncAttributeMaxDynamicSharedMemorySize, GEMM_SMEM);

    dim3 blk(256);
    const int GY = NTOK / 128;   // 128

    // 0) split weights to bf16 hi/lo
    split_w<<<(DREC * HIDDEN / 4) / 256, blk>>>(w_in,   wih,  wil,  DREC * HIDDEN / 4);
    split_w<<<(DREC * HIDDEN / 4) / 256, blk>>>(w_gate, wgh,  wgl,  DREC * HIDDEN / 4);
    split_w<<<(DREC * DREC / 4) / 256, blk>>>(w_a,    wah,  wal,  DREC * DREC / 4);
    split_w<<<(HIDDEN * DREC / 4) / 256, blk>>>(w_out,  woh,  wol,  HIDDEN * DREC / 4);
    split_w<<<(INTER * HIDDEN / 4) / 256, blk>>>(w_mg,   wmgh, wmgl, INTER * HIDDEN / 4);
    split_w<<<(INTER * HIDDEN / 4) / 256, blk>>>(w_mu,   wmuh, wmul, INTER * HIDDEN / 4);
    split_w<<<(HIDDEN * INTER / 4) / 256, blk>>>(w_md,   wmdh, wmdl, HIDDEN * INTER / 4);

    // 1) h = rmsnorm(x, ln1)  (split out)
    rmsnorm_split<<<NTOK, blk>>>(x, ln1_w, hh, hl);

    // 2) xin = h @ w_in^T  (split out)
    mma_gemm<EPI_NONE, true><<<dim3(DREC / 128, GY), blk, GEMM_SMEM>>>(
        hh, hl, wih, wil, nullptr, xinh, xinl, nullptr, DREC, HIDDEN);

    // 3) gate = sigmoid(h @ w_gate^T)  (fp32)
    mma_gemm<EPI_SIGMOID, false><<<dim3(DREC / 128, GY), blk, GEMM_SMEM>>>(
        hh, hl, wgh, wgl, gate, nullptr, nullptr, nullptr, DREC, HIDDEN);

    // 4) a = sigmoid(a_param + xin @ w_a^T)  (fp32)
    mma_gemm<EPI_BIAS_SIGMOID, false><<<dim3(DREC / 128, GY), blk, GEMM_SMEM>>>(
        xinh, xinl, wah, wal, aa, nullptr, nullptr, a_param, DREC, DREC);

    // 5) y = gate * scan(xin, a)  (split out)
    scan_part1<<<(NCHUNKS * NCHAN) / 256, blk>>>(xinh, xinl, aa, hp, P, csum);
    scan_part2<<<NCHAN / 256, blk>>>(csum, carry);
    scan_part3<<<(int)((size_t)NTOK * DREC / 4 / 256), blk>>>(hp, P, gate, carry, yh, yl);

    // 6) xres = x + y @ w_out^T  (fp32)
    mma_gemm<EPI_RESADD, false><<<dim3(HIDDEN / 128, GY), blk, GEMM_SMEM>>>(
        yh, yl, woh, wol, xres, nullptr, nullptr, x, HIDDEN, DREC);

    // 7) h2 = rmsnorm(xres, ln2)  (split out)
    rmsnorm_split<<<NTOK, blk>>>(xres, ln2_w, h2h, h2l);

    // 8) mg = h2 @ w_mlp_gate^T  (fp32)
    mma_gemm<EPI_NONE, false><<<dim3(INTER / 128, GY), blk, GEMM_SMEM>>>(
        h2h, h2l, wmgh, wmgl, mg, nullptr, nullptr, nullptr, INTER, HIDDEN);

    // 9) mu = silu(mg) * (h2 @ w_mlp_up^T)  (split out)
    mma_gemm<EPI_SILU_AUX_MUL, true><<<dim3(INTER / 128, GY), blk, GEMM_SMEM>>>(
        h2h, h2l, wmuh, wmul, nullptr, muh, mul, mg, INTER, HIDDEN);

    // 10) out = xres + mu @ w_mlp_down^T  (fp32)
    mma_gemm<EPI_RESADD, false><<<dim3(HIDDEN / 128, GY), blk, GEMM_SMEM>>>(
        muh, mul, wmdh, wmdl, out, nullptr, nullptr, xres, HIDDEN, INTER);
}

// round 4
// speedup vs baseline: 3.3433x; 1.0600x over previous
#include <cuda_runtime.h>
#include <cuda_bf16.h>
#include <math.h>
#include <stdint.h>

// ---------------------------------------------------------------------------
// HawkBlock: mma.sync bf16 split-3 GEMMs (fused 3-product inner loop,
// 3-stage cp.async pipeline) + parallel scan.
// ---------------------------------------------------------------------------

#define NTOK   16384
#define HIDDEN 1024
#define DREC   2048
#define INTER  4096
#define TLEN   4096
#define NB     4

#define SCHUNK   64
#define NCHUNKS  (TLEN / SCHUNK)   // 64
#define NCHAN    (NB * DREC)       // 8192

typedef __nv_bfloat16  bf16;
typedef __nv_bfloat162 bf162;

// ---- static scratch: activations ----
__device__ bf16  g_h_hi  [(size_t)NTOK * HIDDEN];
__device__ bf16  g_h_lo  [(size_t)NTOK * HIDDEN];
__device__ bf16  g_h2_hi [(size_t)NTOK * HIDDEN];
__device__ bf16  g_h2_lo [(size_t)NTOK * HIDDEN];
__device__ float g_xres  [(size_t)NTOK * HIDDEN];
__device__ bf16  g_xin_hi[(size_t)NTOK * DREC];
__device__ bf16  g_xin_lo[(size_t)NTOK * DREC];
__device__ float g_gate  [(size_t)NTOK * DREC];
__device__ float g_a     [(size_t)NTOK * DREC];
__device__ float g_hp    [(size_t)NTOK * DREC];
__device__ float g_P     [(size_t)NTOK * DREC];
__device__ bf16  g_y_hi  [(size_t)NTOK * DREC];
__device__ bf16  g_y_lo  [(size_t)NTOK * DREC];
__device__ float g_mg    [(size_t)NTOK * INTER];
__device__ bf16  g_mu_hi [(size_t)NTOK * INTER];
__device__ bf16  g_mu_lo [(size_t)NTOK * INTER];
__device__ float g_csum  [2 * NCHUNKS * NCHAN];
__device__ float g_carry [NCHUNKS * NCHAN];

// ---- static scratch: split weights (hi/lo bf16) ----
__device__ bf16 g_wi_hi [(size_t)DREC * HIDDEN],  g_wi_lo [(size_t)DREC * HIDDEN];
__device__ bf16 g_wg_hi [(size_t)DREC * HIDDEN],  g_wg_lo [(size_t)DREC * HIDDEN];
__device__ bf16 g_wa_hi [(size_t)DREC * DREC],    g_wa_lo [(size_t)DREC * DREC];
__device__ bf16 g_wo_hi [(size_t)HIDDEN * DREC],  g_wo_lo [(size_t)HIDDEN * DREC];
__device__ bf16 g_wmg_hi[(size_t)INTER * HIDDEN], g_wmg_lo[(size_t)INTER * HIDDEN];
__device__ bf16 g_wmu_hi[(size_t)INTER * HIDDEN], g_wmu_lo[(size_t)INTER * HIDDEN];
__device__ bf16 g_wmd_hi[(size_t)HIDDEN * INTER], g_wmd_lo[(size_t)HIDDEN * INTER];

// ---------------------------------------------------------------------------
// helpers
// ---------------------------------------------------------------------------
__device__ __forceinline__ uint32_t smem_u32(const void* p) {
    uint32_t a;
    asm("{ .reg .u64 t; cvta.to.shared.u64 t, %1; cvt.u32.u64 %0, t; }"
        : "=r"(a) : "l"(p));
    return a;
}
__device__ __forceinline__ void cp16(uint32_t dst, const void* src) {
    asm volatile("cp.async.cg.shared.global [%0], [%1], 16;"
                 :: "r"(dst), "l"(src));
}
__device__ __forceinline__ void cp_commit() {
    asm volatile("cp.async.commit_group;" ::: "memory");
}
template<int N>
__device__ __forceinline__ void cp_wait() {
    asm volatile("cp.async.wait_group %0;" :: "n"(N) : "memory");
}
__device__ __forceinline__ void ldsm4(uint32_t (&r)[4], uint32_t addr) {
    asm volatile("ldmatrix.sync.aligned.m8n8.x4.shared.b16 {%0,%1,%2,%3}, [%4];"
                 : "=r"(r[0]), "=r"(r[1]), "=r"(r[2]), "=r"(r[3]) : "r"(addr));
}
__device__ __forceinline__ void mma_bf16(float (&d)[4], const uint32_t (&a)[4],
                                         uint32_t b0, uint32_t b1) {
    asm volatile("mma.sync.aligned.m16n8k16.row.col.f32.bf16.bf16.f32 "
                 "{%0,%1,%2,%3}, {%4,%5,%6,%7}, {%8,%9}, {%0,%1,%2,%3};"
                 : "+f"(d[0]), "+f"(d[1]), "+f"(d[2]), "+f"(d[3])
                 : "r"(a[0]), "r"(a[1]), "r"(a[2]), "r"(a[3]), "r"(b0), "r"(b1));
}
__device__ __forceinline__ uint32_t pack_bf2(bf16 a, bf16 b) {
    bf162 t = __halves2bfloat162(a, b);
    return *reinterpret_cast<uint32_t*>(&t);
}
__device__ __forceinline__ void split1(float v, bf16& h, bf16& l) {
    h = __float2bfloat16(v);
    l = __float2bfloat16(v - __bfloat162float(h));
}

// ---------------------------------------------------------------------------
// batched weight split: up to 4 arrays per launch (sizes in float4 units)
// ---------------------------------------------------------------------------
__global__ __launch_bounds__(256) void split_multi(
    const float* __restrict__ s0, bf16* __restrict__ h0, bf16* __restrict__ l0, int n0,
    const float* __restrict__ s1, bf16* __restrict__ h1, bf16* __restrict__ l1, int n1,
    const float* __restrict__ s2, bf16* __restrict__ h2, bf16* __restrict__ l2, int n2,
    const float* __restrict__ s3, bf16* __restrict__ h3, bf16* __restrict__ l3, int n3)
{
    int i = blockIdx.x * 256 + threadIdx.x;
    const float* s; bf16 *hh, *ll; int j = i;
    if (j < n0) { s = s0; hh = h0; ll = l0; }
    else {
        j -= n0;
        if (j < n1) { s = s1; hh = h1; ll = l1; }
        else {
            j -= n1;
            if (j < n2) { s = s2; hh = h2; ll = l2; }
            else {
                j -= n2;
                if (j >= n3) return;
                s = s3; hh = h3; ll = l3;
            }
        }
    }
    float4 v = reinterpret_cast<const float4*>(s)[j];
    bf16 a0, a1, a2, a3, b0, b1, b2, b3;
    split1(v.x, a0, b0); split1(v.y, a1, b1);
    split1(v.z, a2, b2); split1(v.w, a3, b3);
    reinterpret_cast<uint2*>(hh)[j] = make_uint2(pack_bf2(a0, a1), pack_bf2(a2, a3));
    reinterpret_cast<uint2*>(ll)[j] = make_uint2(pack_bf2(b0, b1), pack_bf2(b2, b3));
}

// ---------------------------------------------------------------------------
// RMSNorm -> hi/lo bf16 planes
// ---------------------------------------------------------------------------
__global__ __launch_bounds__(256) void rmsnorm_split(
    const float* __restrict__ x, const float* __restrict__ w,
    bf16* __restrict__ oh, bf16* __restrict__ ol)
{
    int tkn = blockIdx.x;
    int t = threadIdx.x;
    float4 v = reinterpret_cast<const float4*>(x + (size_t)tkn * HIDDEN)[t];
    float s = v.x * v.x + v.y * v.y + v.z * v.z + v.w * v.w;
    #pragma unroll
    for (int o = 16; o > 0; o >>= 1) s += __shfl_xor_sync(0xFFFFFFFFu, s, o);
    __shared__ float ws[8];
    __shared__ float tot_sh;
    if ((t & 31) == 0) ws[t >> 5] = s;
    __syncthreads();
    if (t < 32) {
        float z = (t < 8) ? ws[t] : 0.0f;
        #pragma unroll
        for (int o = 4; o > 0; o >>= 1) z += __shfl_xor_sync(0xFFFFFFFFu, z, o);
        if (t == 0) tot_sh = z;
    }
    __syncthreads();
    float r = rsqrtf(tot_sh * (1.0f / HIDDEN) + 1e-6f);
    float4 wv = reinterpret_cast<const float4*>(w)[t];
    float f0 = v.x * r * wv.x, f1 = v.y * r * wv.y;
    float f2 = v.z * r * wv.z, f3 = v.w * r * wv.w;
    bf16 h0, h1, h2, h3, l0, l1, l2, l3;
    split1(f0, h0, l0); split1(f1, h1, l1);
    split1(f2, h2, l2); split1(f3, h3, l3);
    size_t q = (size_t)tkn * (HIDDEN / 4) + t;
    reinterpret_cast<uint2*>(oh)[q] = make_uint2(pack_bf2(h0, h1), pack_bf2(h2, h3));
    reinterpret_cast<uint2*>(ol)[q] = make_uint2(pack_bf2(l0, l1), pack_bf2(l2, l3));
}

// ---------------------------------------------------------------------------
// GEMM: C[N=16384, M] = A[N,K] @ W[M,K]^T, bf16 split-3, fp32 accum.
// CTA 128x128, BK=64, 8 warps (warp tile 64x32).
// 3-buffer smem (64KB each: Ah,Al,Bh,Bl 16KB), cp.async depth 2,
// ONE __syncthreads per chunk. Fused inner loop: per k-step load
// Ah/Al/Bh/Bl fragments once, issue hh/hl/lh products.
// ---------------------------------------------------------------------------
#define EPI_NONE          0
#define EPI_SIGMOID       1
#define EPI_BIAS_SIGMOID  2
#define EPI_RESADD        3
#define EPI_SILU_AUX_MUL  4

template<int EPI>
__device__ __forceinline__ float epi_apply(float v, const float* __restrict__ aux,
                                           size_t idx, int col)
{
    if (EPI == EPI_SIGMOID)      return 1.0f / (1.0f + expf(-v));
    if (EPI == EPI_BIAS_SIGMOID) { float z = v + __ldg(&aux[col]);
                                   return 1.0f / (1.0f + expf(-z)); }
    if (EPI == EPI_RESADD)       return v + __ldg(&aux[idx]);
    if (EPI == EPI_SILU_AUX_MUL) { float g = __ldg(&aux[idx]);
                                   return v * (g / (1.0f + expf(-g))); }
    return v;
}

#define STAGE_B   65536u
#define GEMM_SMEM (3 * 65536)

template<int EPI, bool SPLIT>
__global__ __launch_bounds__(256, 1) void mma_gemm(
    const bf16* __restrict__ Ah, const bf16* __restrict__ Al,
    const bf16* __restrict__ Bh, const bf16* __restrict__ Bl,
    float* __restrict__ Cf, bf16* __restrict__ Ch, bf16* __restrict__ Cl,
    const float* __restrict__ aux, int M, int K)
{
    extern __shared__ char smem[];
    const uint32_t sb = smem_u32(smem);
    const int tid = threadIdx.x;
    const int lane = tid & 31;
    const int wid = tid >> 5;
    const int warp_m = wid >> 2;    // 0..1
    const int warp_n = wid & 3;     // 0..3
    const int rowBlock = blockIdx.y * 128;
    const int colBlock = blockIdx.x * 128;
    const int nch = K >> 6;

    const bf16* gp0 = Ah + (size_t)rowBlock * K;
    const bf16* gp1 = Al + (size_t)rowBlock * K;
    const bf16* gp2 = Bh + (size_t)colBlock * K;
    const bf16* gp3 = Bl + (size_t)colBlock * K;

    auto issue = [&](int buf, int c) {
        const int kb = c * 64;
        uint32_t st = sb + (uint32_t)buf * STAGE_B;
        #pragma unroll
        for (int arr = 0; arr < 4; arr++) {
            const bf16* g = (arr == 0) ? gp0 : (arr == 1) ? gp1 : (arr == 2) ? gp2 : gp3;
            uint32_t db = st + arr * 16384u;
            #pragma unroll
            for (int i = 0; i < 4; i++) {
                int u = tid + i * 256;
                int r = u >> 3, cc = u & 7;
                cp16(db + r * 128 + ((cc ^ (r & 7)) << 4),
                     g + (size_t)r * K + kb + cc * 8);
            }
        }
        cp_commit();
    };

    float acc[4][4][4];
    #pragma unroll
    for (int i = 0; i < 4; i++)
        #pragma unroll
        for (int j = 0; j < 4; j++)
            #pragma unroll
            for (int k = 0; k < 4; k++) acc[i][j][k] = 0.0f;

    issue(0, 0);
    if (nch > 1) issue(1, 1);

    // lane-level ldmatrix addressing (row&7 == lane&7 for both A and B)
    const int aRow0 = warp_m * 64 + (lane & 7) + ((lane >> 3) & 1) * 8;
    const int aKh   = (lane >> 4) & 1;
    const int bRow0 = warp_n * 32 + ((lane >> 4) & 1) * 8 + (lane & 7);
    const int bKh   = (lane >> 3) & 1;
    const int swz   = lane & 7;

    for (int c = 0; c < nch; c++) {
        int buf = c % 3;
        if (c + 1 < nch) cp_wait<1>(); else cp_wait<0>();
        __syncthreads();
        // refill the buffer freed by chunk c-1 (== buffer (c+2)%3)
        if (c + 2 < nch) issue((c + 2) % 3, c + 2);

        uint32_t st = sb + (uint32_t)buf * STAGE_B;
        #pragma unroll
        for (int ks = 0; ks < 4; ks++) {
            uint32_t ah[4][4], al[4][4];
            #pragma unroll
            for (int mt = 0; mt < 4; mt++) {
                uint32_t roff = (uint32_t)(aRow0 + mt * 16) * 128
                              + (uint32_t)(((ks * 2 + aKh) ^ swz) << 4);
                ldsm4(ah[mt], st + roff);
                ldsm4(al[mt], st + 16384u + roff);
            }
            uint32_t bh[4][2], bl[4][2];
            #pragma unroll
            for (int p = 0; p < 2; p++) {
                uint32_t roff = (uint32_t)(bRow0 + p * 16) * 128
                              + (uint32_t)(((ks * 2 + bKh) ^ swz) << 4);
                uint32_t t4[4];
                ldsm4(t4, st + 32768u + roff);
                bh[2 * p][0] = t4[0]; bh[2 * p][1] = t4[1];
                bh[2 * p + 1][0] = t4[2]; bh[2 * p + 1][1] = t4[3];
                ldsm4(t4, st + 49152u + roff);
                bl[2 * p][0] = t4[0]; bl[2 * p][1] = t4[1];
                bl[2 * p + 1][0] = t4[2]; bl[2 * p + 1][1] = t4[3];
            }
            // hh
            #pragma unroll
            for (int mt = 0; mt < 4; mt++)
                #pragma unroll
                for (int nt = 0; nt < 4; nt++)
                    mma_bf16(acc[mt][nt], ah[mt], bh[nt][0], bh[nt][1]);
            // hl
            #pragma unroll
            for (int mt = 0; mt < 4; mt++)
                #pragma unroll
                for (int nt = 0; nt < 4; nt++)
                    mma_bf16(acc[mt][nt], ah[mt], bl[nt][0], bl[nt][1]);
            // lh
            #pragma unroll
            for (int mt = 0; mt < 4; mt++)
                #pragma unroll
                for (int nt = 0; nt < 4; nt++)
                    mma_bf16(acc[mt][nt], al[mt], bh[nt][0], bh[nt][1]);
        }
        __syncthreads();
    }

    // epilogue
    #pragma unroll
    for (int mt = 0; mt < 4; mt++) {
        #pragma unroll
        for (int nt = 0; nt < 4; nt++) {
            int col = colBlock + warp_n * 32 + nt * 8 + (lane & 3) * 2;
            #pragma unroll
            for (int half = 0; half < 2; half++) {
                int row = rowBlock + warp_m * 64 + mt * 16 + (lane >> 2) + half * 8;
                size_t idx = (size_t)row * M + col;
                float f0 = epi_apply<EPI>(acc[mt][nt][half * 2 + 0], aux, idx, col);
                float f1 = epi_apply<EPI>(acc[mt][nt][half * 2 + 1], aux, idx + 1, col + 1);
                if (SPLIT) {
                    bf16 h0, h1, l0, l1;
                    split1(f0, h0, l0); split1(f1, h1, l1);
                    *reinterpret_cast<uint32_t*>(Ch + idx) = pack_bf2(h0, h1);
                    *reinterpret_cast<uint32_t*>(Cl + idx) = pack_bf2(l0, l1);
                } else {
                    *reinterpret_cast<float2*>(Cf + idx) = make_float2(f0, f1);
                }
            }
        }
    }
}

// ---------------------------------------------------------------------------
// Parallel Hawk scan (3 passes)
// ---------------------------------------------------------------------------
__global__ __launch_bounds__(256) void scan_part1(
    const bf16* __restrict__ xh, const bf16* __restrict__ xl,
    const float* __restrict__ a,
    float* __restrict__ hp, float* __restrict__ P, float* __restrict__ csum)
{
    int id = blockIdx.x * 256 + threadIdx.x;
    int chunk = id >> 13;
    int chp = id & (NCHAN - 1);
    int b = chp >> 11;
    int d = chp & (DREC - 1);
    size_t base = ((size_t)b * TLEN + (size_t)chunk * SCHUNK) * DREC + d;

    float h = 0.0f, Aacc = 1.0f;
    #pragma unroll 4
    for (int t = 0; t < SCHUNK; t++) {
        size_t idx = base + (size_t)t * DREC;
        float at = __ldg(&a[idx]);
        float xt = __bfloat162float(__ldg(&xh[idx])) + __bfloat162float(__ldg(&xl[idx]));
        float s = sqrtf(fmaf(-at, at, 1.0f) + 1e-8f);
        h = fmaf(at, h, s * xt);
        Aacc *= at;
        hp[idx] = h;
        P[idx] = Aacc;
    }
    csum[(size_t)chunk * NCHAN + chp] = Aacc;
    csum[(size_t)NCHUNKS * NCHAN + (size_t)chunk * NCHAN + chp] = h;
}

__global__ __launch_bounds__(256) void scan_part2(
    const float* __restrict__ csum, float* __restrict__ carry)
{
    int chp = blockIdx.x * 256 + threadIdx.x;
    float h = 0.0f;
    #pragma unroll 8
    for (int c = 0; c < NCHUNKS; c++) {
        carry[(size_t)c * NCHAN + chp] = h;
        float Ac = csum[(size_t)c * NCHAN + chp];
        float hc = csum[(size_t)NCHUNKS * NCHAN + (size_t)c * NCHAN + chp];
        h = fmaf(Ac, h, hc);
    }
}

__global__ __launch_bounds__(256) void scan_part3(
    const float* __restrict__ hp, const float* __restrict__ P,
    const float* __restrict__ gate, const float* __restrict__ carry,
    bf16* __restrict__ yh, bf16* __restrict__ yl)
{
    size_t q = (size_t)blockIdx.x * 256 + threadIdx.x;  // float4 index
    size_t i = q * 4;
    size_t n = i >> 11;
    int d = (int)(i & (DREC - 1));
    int b = (int)(n >> 12);
    int t = (int)(n & (TLEN - 1));
    int c = t >> 6;

    float4 h4 = reinterpret_cast<const float4*>(hp)[q];
    float4 p4 = reinterpret_cast<const float4*>(P)[q];
    float4 g4 = reinterpret_cast<const float4*>(gate)[q];
    float4 cv = *reinterpret_cast<const float4*>(carry + (size_t)c * NCHAN + b * DREC + d);
    float o0 = g4.x * fmaf(p4.x, cv.x, h4.x);
    float o1 = g4.y * fmaf(p4.y, cv.y, h4.y);
    float o2 = g4.z * fmaf(p4.z, cv.z, h4.z);
    float o3 = g4.w * fmaf(p4.w, cv.w, h4.w);
    bf16 h0, h1, h2, h3, l0, l1, l2, l3;
    split1(o0, h0, l0); split1(o1, h1, l1);
    split1(o2, h2, l2); split1(o3, h3, l3);
    reinterpret_cast<uint2*>(yh)[q] = make_uint2(pack_bf2(h0, h1), pack_bf2(h2, h3));
    reinterpret_cast<uint2*>(yl)[q] = make_uint2(pack_bf2(l0, l1), pack_bf2(l2, l3));
}

// ---------------------------------------------------------------------------
// Launch
// ---------------------------------------------------------------------------
#define SYM(p, s) cudaGetSymbolAddress((void**)&p, s)

extern "C" void kernel_launch(void* const* d_in, const int* in_sizes, int n_in,
                              void* d_out, int out_size)
{
    const float* x       = (const float*)d_in[0];
    const float* ln1_w   = (const float*)d_in[1];
    const float* ln2_w   = (const float*)d_in[2];
    const float* w_in    = (const float*)d_in[3];
    const float* w_gate  = (const float*)d_in[4];
    const float* a_param = (const float*)d_in[5];
    const float* w_a     = (const float*)d_in[6];
    const float* w_out   = (const float*)d_in[7];
    const float* w_mg    = (const float*)d_in[8];
    const float* w_mu    = (const float*)d_in[9];
    const float* w_md    = (const float*)d_in[10];
    float* out = (float*)d_out;

    bf16 *hh, *hl, *h2h, *h2l, *xinh, *xinl, *yh, *yl, *muh, *mul;
    float *xres, *gate, *aa, *hp, *P, *mg, *csum, *carry;
    bf16 *wih, *wil, *wgh, *wgl, *wah, *wal, *woh, *wol;
    bf16 *wmgh, *wmgl, *wmuh, *wmul, *wmdh, *wmdl;

    SYM(hh, g_h_hi);   SYM(hl, g_h_lo);
    SYM(h2h, g_h2_hi); SYM(h2l, g_h2_lo);
    SYM(xinh, g_xin_hi); SYM(xinl, g_xin_lo);
    SYM(yh, g_y_hi);   SYM(yl, g_y_lo);
    SYM(muh, g_mu_hi); SYM(mul, g_mu_lo);
    SYM(xres, g_xres); SYM(gate, g_gate); SYM(aa, g_a);
    SYM(hp, g_hp);     SYM(P, g_P);       SYM(mg, g_mg);
    SYM(csum, g_csum); SYM(carry, g_carry);
    SYM(wih, g_wi_hi);  SYM(wil, g_wi_lo);
    SYM(wgh, g_wg_hi);  SYM(wgl, g_wg_lo);
    SYM(wah, g_wa_hi);  SYM(wal, g_wa_lo);
    SYM(woh, g_wo_hi);  SYM(wol, g_wo_lo);
    SYM(wmgh, g_wmg_hi); SYM(wmgl, g_wmg_lo);
    SYM(wmuh, g_wmu_hi); SYM(wmul, g_wmu_lo);
    SYM(wmdh, g_wmd_hi); SYM(wmdl, g_wmd_lo);

    cudaFuncSetAttribute(mma_gemm<EPI_NONE, true>,          cudaFuncAttributeMaxDynamicSharedMemorySize, GEMM_SMEM);
    cudaFuncSetAttribute(mma_gemm<EPI_NONE, false>,         cudaFuncAttributeMaxDynamicSharedMemorySize, GEMM_SMEM);
    cudaFuncSetAttribute(mma_gemm<EPI_SIGMOID, false>,      cudaFuncAttributeMaxDynamicSharedMemorySize, GEMM_SMEM);
    cudaFuncSetAttribute(mma_gemm<EPI_BIAS_SIGMOID, false>, cudaFuncAttributeMaxDynamicSharedMemorySize, GEMM_SMEM);
    cudaFuncSetAttribute(mma_gemm<EPI_RESADD, false>,       cudaFuncAttributeMaxDynamicSharedMemorySize, GEMM_SMEM);
    cudaFuncSetAttribute(mma_gemm<EPI_SILU_AUX_MUL, true>,  cudaFuncAttributeMaxDynamicSharedMemorySize, GEMM_SMEM);

    dim3 blk(256);
    const int GY = NTOK / 128;   // 128

    const int n_ih = DREC * HIDDEN / 4;   // 524288
    const int n_aa = DREC * DREC / 4;     // 1048576
    const int n_mh = INTER * HIDDEN / 4;  // 1048576

    // launch 0: split w_in, w_gate, w_a  (4th slot = dup with n=0)
    split_multi<<<(n_ih + n_ih + n_aa + 255) / 256, blk>>>(
        w_in, wih, wil, n_ih,
        w_gate, wgh, wgl, n_ih,
        w_a, wah, wal, n_aa,
        w_a, wah, wal, 0);
    // launch 1: split w_out, w_mg, w_mu, w_md
    split_multi<<<(n_ih + 3 * n_mh + 255) / 256, blk>>>(
        w_out, woh, wol, n_ih,
        w_mg, wmgh, wmgl, n_mh,
        w_mu, wmuh, wmul, n_mh,
        w_md, wmdh, wmdl, n_mh);

    // launch 2: h = rmsnorm(x, ln1)
    rmsnorm_split<<<NTOK, blk>>>(x, ln1_w, hh, hl);

    // launch 3: xin = h @ w_in^T
    mma_gemm<EPI_NONE, true><<<dim3(DREC / 128, GY), blk, GEMM_SMEM>>>(
        hh, hl, wih, wil, nullptr, xinh, xinl, nullptr, DREC, HIDDEN);

    // launch 4: gate = sigmoid(h @ w_gate^T)
    mma_gemm<EPI_SIGMOID, false><<<dim3(DREC / 128, GY), blk, GEMM_SMEM>>>(
        hh, hl, wgh, wgl, gate, nullptr, nullptr, nullptr, DREC, HIDDEN);

    // launch 5 (ncu -s 5 -c 1 profiles this): a = sigmoid(a_param + xin @ w_a^T)
    mma_gemm<EPI_BIAS_SIGMOID, false><<<dim3(DREC / 128, GY), blk, GEMM_SMEM>>>(
        xinh, xinl, wah, wal, aa, nullptr, nullptr, a_param, DREC, DREC);

    // scan
    scan_part1<<<(NCHUNKS * NCHAN) / 256, blk>>>(xinh, xinl, aa, hp, P, csum);
    scan_part2<<<NCHAN / 256, blk>>>(csum, carry);
    scan_part3<<<(int)((size_t)NTOK * DREC / 4 / 256), blk>>>(hp, P, gate, carry, yh, yl);

    // xres = x + y @ w_out^T
    mma_gemm<EPI_RESADD, false><<<dim3(HIDDEN / 128, GY), blk, GEMM_SMEM>>>(
        yh, yl, woh, wol, xres, nullptr, nullptr, x, HIDDEN, DREC);

    // h2 = rmsnorm(xres, ln2)
    rmsnorm_split<<<NTOK, blk>>>(xres, ln2_w, h2h, h2l);

    // mg = h2 @ w_mlp_gate^T
    mma_gemm<EPI_NONE, false><<<dim3(INTER / 128, GY), blk, GEMM_SMEM>>>(
        h2h, h2l, wmgh, wmgl, mg, nullptr, nullptr, nullptr, INTER, HIDDEN);

    // mu = silu(mg) * (h2 @ w_mlp_up^T)
    mma_gemm<EPI_SILU_AUX_MUL, true><<<dim3(INTER / 128, GY), blk, GEMM_SMEM>>>(
        h2h, h2l, wmuh, wmul, nullptr, muh, mul, mg, INTER, HIDDEN);

    // out = xres + mu @ w_mlp_down^T
    mma_gemm<EPI_RESADD, false><<<dim3(HIDDEN / 128, GY), blk, GEMM_SMEM>>>(
        muh, mul, wmdh, wmdl, out, nullptr, nullptr, xres, HIDDEN, INTER);
}